// round 10
// baseline (speedup 1.0000x reference)
#include <cuda_runtime.h>
#include <cuda_bf16.h>
#include <mma.h>
#include <math_constants.h>
#include <cstdint>

using namespace nvcuda;

#define Nn 2
#define Ll 2048
#define Hh 8
#define Ee 64
#define Mm 2048
#define HEADS 16
#define NLH (HEADS*Ll)

#define NRM   0.3535533905932738f
#define HNRM2 0.0625f
#define RATIO 0.022097086912079608f
#define KEPS  1e-4f
#define EPSZ  1e-6f

// ---------------- scratch ----------------
__device__ float g_Dq[(size_t)HEADS*Ll*Mm];
__device__ float g_Dk[(size_t)HEADS*Ll*Mm];
__device__ float g_diag[2][NLH];
__device__ float g_pmax[(size_t)32*16*Ll];
__device__ float g_SUB[32*Ll];
__device__ __nv_bfloat16 g_Xhi[(size_t)2*HEADS*Ll*Ee];
__device__ __nv_bfloat16 g_Xlo[(size_t)2*HEADS*Ll*Ee];
__device__ __nv_bfloat16 g_Phi[(size_t)Mm*Ee];
__device__ __nv_bfloat16 g_Plo[(size_t)Mm*Ee];
__device__ __nv_bfloat16 g_VThi[(size_t)HEADS*Ee*Ll];
__device__ __nv_bfloat16 g_VTlo[(size_t)HEADS*Ee*Ll];
__device__ __nv_bfloat16 g_Bhi[(size_t)HEADS*80*Mm];   // rows 0-63 kv^T, row 64 ksum
__device__ __nv_bfloat16 g_Blo[(size_t)HEADS*80*Mm];

__device__ __forceinline__ void split1(float v, __nv_bfloat16& hi, __nv_bfloat16& lo) {
    hi = __float2bfloat16_rn(v);
    lo = __float2bfloat16_rn(v - __bfloat162float(hi));
}
__device__ __forceinline__ void split2pack(float a, float b, uint32_t& hi, uint32_t& lo) {
    __nv_bfloat16 ha, la, hb, lb;
    split1(a, ha, la); split1(b, hb, lb);
    __nv_bfloat162 H = __halves2bfloat162(ha, hb), L = __halves2bfloat162(la, lb);
    hi = *(uint32_t*)&H; lo = *(uint32_t*)&L;
}

__device__ __forceinline__ uint32_t smem_u32(const void* p) {
    uint32_t a;
    asm("{ .reg .u64 t; cvta.to.shared.u64 t, %1; cvt.u32.u64 %0, t; }" : "=r"(a) : "l"(p));
    return a;
}
__device__ __forceinline__ void cp16(uint32_t s, const void* g) {
    asm volatile("cp.async.cg.shared.global [%0], [%1], 16;" :: "r"(s), "l"(g));
}
#define CP_COMMIT() asm volatile("cp.async.commit_group;" ::: "memory")
#define CP_WAIT1()  asm volatile("cp.async.wait_group 1;" ::: "memory")
#define CP_WAIT0()  asm volatile("cp.async.wait_group 0;" ::: "memory")
#define BAR_SYNC(id, cnt)   asm volatile("bar.sync %0, %1;"   :: "r"(id), "r"(cnt) : "memory")
#define BAR_ARRIVE(id, cnt) asm volatile("bar.arrive %0, %1;" :: "r"(id), "r"(cnt) : "memory")

typedef wmma::fragment<wmma::matrix_a, 16, 16, 16, __nv_bfloat16, wmma::row_major> FragA;
typedef wmma::fragment<wmma::matrix_a, 16, 16, 16, __nv_bfloat16, wmma::col_major> FragAc;
typedef wmma::fragment<wmma::matrix_b, 16, 16, 16, __nv_bfloat16, wmma::col_major> FragB;
typedef wmma::fragment<wmma::accumulator, 16, 16, 16, float> FragC;

// ================== K0: prep ==================
__global__ __launch_bounds__(256) void k_prep(const float* __restrict__ q,
                                              const float* __restrict__ kk,
                                              const float* __restrict__ P)
{
    int g = blockIdx.x * 256 + threadIdx.x;
    int w = g >> 5, lane = g & 31;
    if (w < 2*NLH) {
        int which = (w >= NLH) ? 1 : 0;
        int r = which ? (w - NLH) : w;
        int head = r >> 11, l = r & (Ll - 1);
        int n = head >> 3, h = head & 7;
        const float* x = (which ? kk : q) + ((size_t)((n*Ll + l)*Hh + h))*Ee;
        float2 f = *(const float2*)(x + 2*lane);
        float s = f.x*f.x + f.y*f.y;
        #pragma unroll
        for (int o = 16; o; o >>= 1) s += __shfl_xor_sync(0xffffffffu, s, o);
        if (lane == 0) g_diag[which][r] = HNRM2 * s;
        uint32_t hi, lo; split2pack(f.x*NRM, f.y*NRM, hi, lo);
        size_t base = ((size_t)(which*HEADS + head)*Ll + l)*Ee;
        *(uint32_t*)(g_Xhi + base + 2*lane) = hi;
        *(uint32_t*)(g_Xlo + base + 2*lane) = lo;
    } else {
        int m = w - 2*NLH;
        const float* p = P + (size_t)m*Ee;
        float2 f = *(const float2*)(p + 2*lane);
        uint32_t hi, lo; split2pack(f.x, f.y, hi, lo);
        *(uint32_t*)(g_Phi + (size_t)m*Ee + 2*lane) = hi;
        *(uint32_t*)(g_Plo + (size_t)m*Ee + 2*lane) = lo;
    }
}

// ================== K0b: v -> vT split ==================
__global__ __launch_bounds__(256) void k_vt(const float* __restrict__ V)
{
    __shared__ __nv_bfloat16 sh[2][64][136];
    const int head = blockIdx.y, n = head >> 3, h = head & 7;
    const int s0 = blockIdx.x * 128;
    const int tid = threadIdx.x;

    {
        int s = tid >> 1, eh = (tid & 1) * 32;
        const float* vp = V + ((size_t)((n*Ll + s0 + s)*Hh + h))*Ee + eh;
        #pragma unroll
        for (int j = 0; j < 8; j++) {
            float4 f = *(const float4*)(vp + j*4);
            float vv[4] = {f.x, f.y, f.z, f.w};
            #pragma unroll
            for (int i = 0; i < 4; i++) {
                __nv_bfloat16 hb, lb; split1(vv[i], hb, lb);
                int e = eh + j*4 + i;
                sh[0][e][s] = hb;
                sh[1][e][s] = lb;
            }
        }
    }
    __syncthreads();
    {
        int e = tid >> 2, sc = (tid & 3) * 32;
        #pragma unroll
        for (int p = 0; p < 2; p++) {
            __nv_bfloat16* dst = (p ? g_VTlo : g_VThi) + ((size_t)(head*Ee + e))*Ll + s0 + sc;
            const uint32_t* src = (const uint32_t*)&sh[p][e][sc];
            #pragma unroll
            for (int i = 0; i < 16; i++) ((uint32_t*)dst)[i] = src[i];
        }
    }
}

// ================== K1: featurize — persistent stripe (16 tiles) ==========
#define FT_A     36864
#define FT_STG   110592
#define FT_SMEM  178176
__global__ __launch_bounds__(512, 1) void k_feat()
{
    extern __shared__ char smem[];
    const uint32_t sb = smem_u32(smem);
    const int wh = blockIdx.z;
    const int which = wh >> 4, head = wh & 15;
    const int m0 = blockIdx.x * 128;
    const int tid = threadIdx.x, wid = tid >> 5;
    float* __restrict__ Dash = which ? g_Dk : g_Dq;

    const __nv_bfloat16* Xhi = g_Xhi + (size_t)wh*Ll*Ee;
    const __nv_bfloat16* Xlo = g_Xlo + (size_t)wh*Ll*Ee;

    #pragma unroll
    for (int j = 0; j < 4; j++) {
        int g = tid + j*512;
        int plane = g >> 10, r = (g >> 3) & 127, c = g & 7;
        const __nv_bfloat16* src = (plane ? g_Plo : g_Phi) + (size_t)(m0 + r)*Ee + c*8;
        cp16(sb + plane*18432 + (r*72 + c*8)*2, src);
    }
    #pragma unroll
    for (int j = 0; j < 4; j++) {
        int g = tid + j*512;
        int plane = g >> 10, r = (g >> 3) & 127, c = g & 7;
        const __nv_bfloat16* src = (plane ? Xlo : Xhi) + (size_t)r*Ee + c*8;
        cp16(sb + FT_A + plane*18432 + (r*72 + c*8)*2, src);
    }
    CP_COMMIT();
    #pragma unroll
    for (int j = 0; j < 4; j++) {
        int g = tid + j*512;
        int plane = g >> 10, r = (g >> 3) & 127, c = g & 7;
        const __nv_bfloat16* src = (plane ? Xlo : Xhi) + (size_t)(128 + r)*Ee + c*8;
        cp16(sb + FT_A + 36864 + plane*18432 + (r*72 + c*8)*2, src);
    }
    CP_COMMIT();

    const int warp_l = (wid & 3) * 32, warp_m = (wid >> 2) * 32;
    float* stage = (float*)(smem + FT_STG);
    const __nv_bfloat16* Bhi = (const __nv_bfloat16*)smem;
    const __nv_bfloat16* Blo = Bhi + 9216;

    for (int t = 0; t < 16; t++) {
        if (t < 15) { CP_WAIT1(); } else { CP_WAIT0(); }
        __syncthreads();

        const __nv_bfloat16* Ahi = (const __nv_bfloat16*)(smem + FT_A + (t & 1)*36864);
        const __nv_bfloat16* Alo = Ahi + 9216;

        FragC c[2][2];
        #pragma unroll
        for (int i = 0; i < 2; i++)
            #pragma unroll
            for (int j = 0; j < 2; j++) wmma::fill_fragment(c[i][j], 0.0f);

        #pragma unroll
        for (int k = 0; k < 4; k++) {
            FragA ahi[2], alo[2];
            #pragma unroll
            for (int i = 0; i < 2; i++) {
                wmma::load_matrix_sync(ahi[i], Ahi + (warp_l + i*16)*72 + k*16, 72);
                wmma::load_matrix_sync(alo[i], Alo + (warp_l + i*16)*72 + k*16, 72);
            }
            #pragma unroll
            for (int j = 0; j < 2; j++) {
                FragB bhi, blo;
                wmma::load_matrix_sync(bhi, Bhi + (warp_m + j*16)*72 + k*16, 72);
                wmma::load_matrix_sync(blo, Blo + (warp_m + j*16)*72 + k*16, 72);
                #pragma unroll
                for (int i = 0; i < 2; i++) {
                    wmma::mma_sync(c[i][j], ahi[i], bhi, c[i][j]);
                    wmma::mma_sync(c[i][j], ahi[i], blo, c[i][j]);
                    wmma::mma_sync(c[i][j], alo[i], bhi, c[i][j]);
                }
            }
        }

        #pragma unroll
        for (int i = 0; i < 2; i++)
            #pragma unroll
            for (int j = 0; j < 2; j++)
                wmma::store_matrix_sync(stage + (warp_l + i*16)*132 + warp_m + j*16,
                                        c[i][j], 132, wmma::mem_row_major);
        __syncthreads();

        if (t + 2 < 16) {
            #pragma unroll
            for (int j = 0; j < 4; j++) {
                int g = tid + j*512;
                int plane = g >> 10, r = (g >> 3) & 127, cc = g & 7;
                const __nv_bfloat16* src = (plane ? Xlo : Xhi)
                    + (size_t)((t + 2)*128 + r)*Ee + cc*8;
                cp16(sb + FT_A + (t & 1)*36864 + plane*18432 + (r*72 + cc*8)*2, src);
            }
            CP_COMMIT();
        }

        {
            int row = tid >> 2;
            int l = t*128 + row;
            float rm = -CUDART_INF_F;
            float* dst = Dash + (size_t)(head*Ll + l)*Mm + m0;
            const float* srcr = stage + row*132;
            #pragma unroll
            for (int j = 0; j < 8; j++) {
                int col = (tid & 3)*4 + j*16;
                float4 v = *(const float4*)(srcr + col);
                rm = fmaxf(rm, fmaxf(fmaxf(v.x, v.y), fmaxf(v.z, v.w)));
                *(float4*)(dst + col) = v;
            }
            rm = fmaxf(rm, __shfl_xor_sync(0xffffffffu, rm, 1));
            rm = fmaxf(rm, __shfl_xor_sync(0xffffffffu, rm, 2));
            if ((tid & 3) == 0)
                g_pmax[((size_t)wh*16 + blockIdx.x)*Ll + l] = rm;
        }
    }
}

// ================== K1b: rowmax reduce + diag fold ==================
__global__ __launch_bounds__(256) void k_rmax()
{
    int gw = (blockIdx.x * 256 + threadIdx.x) >> 5;
    int lane = threadIdx.x & 31;
    int wh = gw >> 6;
    int l = (gw & 63) * 32 + lane;
    float m = -CUDART_INF_F;
    #pragma unroll
    for (int mt = 0; mt < 16; mt++)
        m = fmaxf(m, g_pmax[((size_t)wh*16 + mt)*Ll + l]);
    g_SUB[wh*Ll + l] = g_diag[wh >> 4][(wh & 15)*Ll + l] + m;
}

// ================== K2: kv — warp-specialized producer/consumer ==========
// warps 0-3: MMA consumers (also own B cp.async); warps 4-7: raw cp.async + exp/split.
// smem: RAW 2x16384 @0 | A 2x(hi 8704 + lo 8704) @32768 | B 3x10240 @67584
// named barriers: 1,2 = A-full(buf), 3,4 = A-free(buf), 5 = producer grp, 6 = consumer grp
#define KV_A    32768
#define KV_B    67584
#define KV_KSS  67584           // reused post-loop (B dead after last MMA)
#define KV_SMEM 98304
__global__ __launch_bounds__(256, 2) void k_kv()
{
    extern __shared__ char smem[];
    const uint32_t sb = smem_u32(smem);

    const int head = blockIdx.y;
    const int m0 = blockIdx.x * 128;
    const int tid = threadIdx.x;

    if (tid >= 128) {
        // producer prologue: raw(0), raw(1)
        const int t2 = tid - 128;
        #pragma unroll
        for (int tt = 0; tt < 2; tt++) {
            const float* srcK = g_Dk + (size_t)(head*Ll + tt*32)*Mm + m0;
            uint32_t dK = sb + tt*16384;
            #pragma unroll
            for (int j = 0; j < 8; j++) {
                int g = t2 + j*128, row = g >> 5, col = (g & 31)*4;
                cp16(dK + (row*128 + col)*4, srcK + (size_t)row*Mm + col);
            }
            CP_COMMIT();
        }
    } else {
        // consumer prologue: B(0), B(1); pre-arrive the two A-free barriers
        #pragma unroll
        for (int tt = 0; tt < 2; tt++) {
            uint32_t dB = sb + KV_B + tt*10240;
            #pragma unroll
            for (int j = 0; j < 4; j++) {
                int g = tid + j*128, plane = g >> 8, rem = g & 255, row = rem >> 2, cc = rem & 3;
                const __nv_bfloat16* src = (plane ? g_VTlo : g_VThi)
                    + (size_t)(head*Ee + row)*Ll + tt*32 + cc*8;
                cp16(dB + plane*5120 + (row*40 + cc*8)*2, src);
            }
            CP_COMMIT();
        }
        BAR_ARRIVE(3, 256);
        BAR_ARRIVE(4, 256);
    }

    float ksp[32];
    FragC c[2][4];

    if (tid >= 128) {
        // ---------------- producer / transform warps ----------------
        const int t2 = tid - 128;
        const int s_loc = t2 >> 2, mb = (t2 & 3) * 32;
        const float* SUBp = g_SUB + (16 + head)*Ll + s_loc;
        #pragma unroll
        for (int j = 0; j < 32; j++) ksp[j] = 0.0f;

        for (int t = 0; t < 64; t++) {
            BAR_SYNC(3 + (t & 1), 256);                   // A-buf(t&1) free
            if (t < 63) { CP_WAIT1(); } else { CP_WAIT0(); }
            BAR_SYNC(5, 128);                              // raw(t) visible to group

            const float* RK = (const float*)(smem + (t & 1)*16384) + s_loc*128 + mb;
            const float sub = SUBp[t*32];
            char* Abase = smem + KV_A + (t & 1)*17408;
            const uint32_t offb = (uint32_t)(s_loc*136 + mb)*2;
            #pragma unroll
            for (int qq = 0; qq < 4; qq++) {
                float4 f0 = *(const float4*)(RK + qq*8);
                float4 f1 = *(const float4*)(RK + qq*8 + 4);
                float k0 = RATIO * (__expf(f0.x - sub) + KEPS);
                float k1 = RATIO * (__expf(f0.y - sub) + KEPS);
                float k2 = RATIO * (__expf(f0.z - sub) + KEPS);
                float k3 = RATIO * (__expf(f0.w - sub) + KEPS);
                float k4 = RATIO * (__expf(f1.x - sub) + KEPS);
                float k5 = RATIO * (__expf(f1.y - sub) + KEPS);
                float k6 = RATIO * (__expf(f1.z - sub) + KEPS);
                float k7 = RATIO * (__expf(f1.w - sub) + KEPS);
                ksp[qq*8+0] += k0; ksp[qq*8+1] += k1; ksp[qq*8+2] += k2; ksp[qq*8+3] += k3;
                ksp[qq*8+4] += k4; ksp[qq*8+5] += k5; ksp[qq*8+6] += k6; ksp[qq*8+7] += k7;
                uint32_t h0, l0v, h1, l1v, h2, l2v, h3, l3v;
                split2pack(k0, k1, h0, l0v); split2pack(k2, k3, h1, l1v);
                split2pack(k4, k5, h2, l2v); split2pack(k6, k7, h3, l3v);
                *(uint4*)(Abase + offb + qq*16)        = make_uint4(h0, h1, h2, h3);
                *(uint4*)(Abase + 8704 + offb + qq*16) = make_uint4(l0v, l1v, l2v, l3v);
            }
            BAR_SYNC(5, 128);                              // all raw(t) reads done
            if (t + 2 < 64) {                              // refill raw buf (t&1)
                const float* srcK = g_Dk + (size_t)(head*Ll + (t+2)*32)*Mm + m0;
                uint32_t dK = sb + (t & 1)*16384;
                #pragma unroll
                for (int j = 0; j < 8; j++) {
                    int g = t2 + j*128, row = g >> 5, col = (g & 31)*4;
                    cp16(dK + (row*128 + col)*4, srcK + (size_t)row*Mm + col);
                }
                CP_COMMIT();
            }
            BAR_ARRIVE(1 + (t & 1), 256);                  // A(t) full
        }
    } else {
        // ---------------- MMA consumer warps ----------------
        const int wid = tid >> 5;
        const int warp_m = wid * 32;
        #pragma unroll
        for (int i = 0; i < 2; i++)
            #pragma unroll
            for (int j = 0; j < 4; j++) wmma::fill_fragment(c[i][j], 0.0f);

        for (int t = 0; t < 64; t++) {
            if (t < 63) { CP_WAIT1(); } else { CP_WAIT0(); }
            BAR_SYNC(6, 128);                              // B(t) visible; MMA(t-1) smem reads done
            if (t + 2 < 64) {                              // refill B buf (t+2)%3
                uint32_t dB = sb + KV_B + ((t + 2) % 3)*10240;
                #pragma unroll
                for (int j = 0; j < 4; j++) {
                    int g = tid + j*128, plane = g >> 8, rem = g & 255, row = rem >> 2, cc = rem & 3;
                    const __nv_bfloat16* src = (plane ? g_VTlo : g_VThi)
                        + (size_t)(head*Ee + row)*Ll + (t+2)*32 + cc*8;
                    cp16(dB + plane*5120 + (row*40 + cc*8)*2, src);
                }
                CP_COMMIT();
            }
            BAR_SYNC(1 + (t & 1), 256);                    // A(t) ready

            const __nv_bfloat16* Ahi = (const __nv_bfloat16*)(smem + KV_A + (t & 1)*17408);
            const __nv_bfloat16* Alo = Ahi + 4352;         // +8704 bytes
            const __nv_bfloat16* Bh  = (const __nv_bfloat16*)(smem + KV_B + (t % 3)*10240);
            const __nv_bfloat16* Bl  = Bh + 2560;

            #pragma unroll
            for (int k = 0; k < 2; k++) {
                FragAc ahi[2], alo[2];
                #pragma unroll
                for (int i = 0; i < 2; i++) {
                    wmma::load_matrix_sync(ahi[i], Ahi + (k*16)*136 + warp_m + i*16, 136);
                    wmma::load_matrix_sync(alo[i], Alo + (k*16)*136 + warp_m + i*16, 136);
                }
                #pragma unroll
                for (int j = 0; j < 4; j++) {
                    FragB bhi, blo;
                    wmma::load_matrix_sync(bhi, Bh + (j*16)*40 + k*16, 40);
                    wmma::load_matrix_sync(blo, Bl + (j*16)*40 + k*16, 40);
                    #pragma unroll
                    for (int i = 0; i < 2; i++) {
                        wmma::mma_sync(c[i][j], ahi[i], bhi, c[i][j]);
                        wmma::mma_sync(c[i][j], ahi[i], blo, c[i][j]);
                        wmma::mma_sync(c[i][j], alo[i], bhi, c[i][j]);
                    }
                }
            }
            BAR_ARRIVE(3 + (t & 1), 256);                  // A(t) free
        }
    }

    __syncthreads();
    float* stage = (float*)smem;                           // C: [m + e*132] f32
    float* KSS = (float*)(smem + KV_KSS);                  // [32 s][128 m]
    if (tid < 128) {
        const int wid = tid >> 5;
        const int warp_m = wid * 32;
        #pragma unroll
        for (int i = 0; i < 2; i++)
            #pragma unroll
            for (int j = 0; j < 4; j++)
                wmma::store_matrix_sync(stage + (warp_m + i*16) + (j*16)*132,
                                        c[i][j], 132, wmma::mem_col_major);
    } else {
        const int t2 = tid - 128;
        const int s_loc = t2 >> 2, mb = (t2 & 3) * 32;
        #pragma unroll
        for (int j = 0; j < 32; j++) KSS[s_loc*128 + mb + j] = ksp[j];
    }
    __syncthreads();
    {
        int e = tid >> 2, mo = (tid & 3) * 32;
        const float* src = stage + e*132 + mo;
        __nv_bfloat16* dhi = g_Bhi + (size_t)(head*80 + e)*Mm + m0 + mo;
        __nv_bfloat16* dlo = g_Blo + (size_t)(head*80 + e)*Mm + m0 + mo;
        #pragma unroll
        for (int j = 0; j < 32; j += 2) {
            uint32_t hi, lo; split2pack(src[j], src[j+1], hi, lo);
            *(uint32_t*)(dhi + j) = hi;
            *(uint32_t*)(dlo + j) = lo;
        }
    }
    if (tid >= 128) {
        int t2 = tid - 128;
        float s = 0.0f;
        #pragma unroll
        for (int j = 0; j < 32; j++) s += KSS[j*128 + t2];
        __nv_bfloat16 hb, lb; split1(s, hb, lb);
        g_Bhi[(size_t)(head*80 + 64)*Mm + m0 + t2] = hb;
        g_Blo[(size_t)(head*80 + 64)*Mm + m0 + t2] = lb;
    }
}

// ================== K3: out (round-8 structure, N=80 incl. denominator) ====
#define O_AH    36864
#define O_AL    47104
#define O_B     57344
#define O_SUBL  95744
#define O_SMEM  96256
__global__ __launch_bounds__(256, 2) void k_out(float* __restrict__ out)
{
    extern __shared__ char smem[];
    const uint32_t sb = smem_u32(smem);
    __nv_bfloat16* Ah = (__nv_bfloat16*)(smem + O_AH);
    __nv_bfloat16* Al = (__nv_bfloat16*)(smem + O_AL);
    float* SUBL = (float*)(smem + O_SUBL);

    const int head = blockIdx.y, n = head >> 3, h = head & 7;
    const int l0 = blockIdx.x * 128;
    const int tid = threadIdx.x, wid = tid >> 5;

    #pragma unroll
    for (int t = 0; t < 2; t++) {
        const float* srcQ = g_Dq + (size_t)(head*Ll + l0)*Mm + t*32;
        uint32_t dQ = sb + t*18432;
        #pragma unroll
        for (int j = 0; j < 4; j++) {
            int g = tid + j*256, l = g >> 3, col = (g & 7)*4;
            cp16(dQ + (l*36 + col)*4, srcQ + (size_t)l*Mm + col);
        }
        uint32_t dB = sb + O_B + t*12800;
        #pragma unroll
        for (int j = 0; j < 3; j++) {
            int g = tid + j*256;
            if (g < 640) {
                int plane = g / 320, q2 = g % 320, row = q2 >> 2, cc = q2 & 3;
                const __nv_bfloat16* src = (plane ? g_Blo : g_Bhi)
                    + (size_t)(head*80 + row)*Mm + t*32 + cc*8;
                cp16(dB + plane*6400 + (row*40 + cc*8)*2, src);
            }
        }
        CP_COMMIT();
    }

    if (tid < 128)
        SUBL[tid] = g_SUB[head*Ll + l0 + tid];

    const int m2 = (tid & 15) * 2, lg = (tid >> 4) * 8;
    const int warp_l = wid * 16;

    FragC c[5];
    #pragma unroll
    for (int j = 0; j < 5; j++) wmma::fill_fragment(c[j], 0.0f);

    for (int t = 0; t < 64; t++) {
        if (t < 63) { CP_WAIT1(); } else { CP_WAIT0(); }
        __syncthreads();

        const float* RQ = (const float*)(smem + (t & 1)*18432);

        #pragma unroll
        for (int i = 0; i < 8; i++) {
            int l = lg + i;
            float2 f = *(const float2*)(RQ + l*36 + m2);
            float sub = SUBL[l];
            float q0 = RATIO * (__expf(f.x - sub) + KEPS);
            float q1 = RATIO * (__expf(f.y - sub) + KEPS);
            uint32_t hi, lo; split2pack(q0, q1, hi, lo);
            *(uint32_t*)&Ah[l*40 + m2] = hi;
            *(uint32_t*)&Al[l*40 + m2] = lo;
        }
        __syncthreads();

        if (t + 2 < 64) {
            const int m1 = (t + 2) * 32;
            const float* srcQ = g_Dq + (size_t)(head*Ll + l0)*Mm + m1;
            uint32_t dQ = sb + (t & 1)*18432;
            #pragma unroll
            for (int j = 0; j < 4; j++) {
                int g = tid + j*256, l = g >> 3, col = (g & 7)*4;
                cp16(dQ + (l*36 + col)*4, srcQ + (size_t)l*Mm + col);
            }
            uint32_t dB = sb + O_B + ((t + 2) % 3)*12800;
            #pragma unroll
            for (int j = 0; j < 3; j++) {
                int g = tid + j*256;
                if (g < 640) {
                    int plane = g / 320, q2 = g % 320, row = q2 >> 2, cc = q2 & 3;
                    const __nv_bfloat16* src = (plane ? g_Blo : g_Bhi)
                        + (size_t)(head*80 + row)*Mm + m1 + cc*8;
                    cp16(dB + plane*6400 + (row*40 + cc*8)*2, src);
                }
            }
            CP_COMMIT();
        }

        const __nv_bfloat16* Bh = (const __nv_bfloat16*)(smem + O_B + (t % 3)*12800);
        const __nv_bfloat16* Bl = Bh + 3200;

        #pragma unroll
        for (int k = 0; k < 2; k++) {
            FragA ahi, alo;
            wmma::load_matrix_sync(ahi, Ah + warp_l*40 + k*16, 40);
            wmma::load_matrix_sync(alo, Al + warp_l*40 + k*16, 40);
            #pragma unroll
            for (int j = 0; j < 5; j++) {
                FragB bhi, blo;
                wmma::load_matrix_sync(bhi, Bh + (j*16)*40 + k*16, 40);
                wmma::load_matrix_sync(blo, Bl + (j*16)*40 + k*16, 40);
                wmma::mma_sync(c[j], ahi, bhi, c[j]);
                wmma::mma_sync(c[j], ahi, blo, c[j]);
                wmma::mma_sync(c[j], alo, bhi, c[j]);
            }
        }
    }

    __syncthreads();
    float* stage = (float*)smem;  // [l][84]
    #pragma unroll
    for (int j = 0; j < 5; j++)
        wmma::store_matrix_sync(stage + warp_l*84 + j*16, c[j], 84, wmma::mem_row_major);
    __syncthreads();
    {
        int l = tid >> 1, ec = (tid & 1) * 32;
        float z = 1.0f / (stage[l*84 + 64] + EPSZ);
        float* dst = out + ((size_t)((n*Ll + l0 + l)*Hh + h))*Ee + ec;
        const float* src = stage + l*84 + ec;
        #pragma unroll
        for (int j = 0; j < 8; j++) {
            float4 v = *(const float4*)(src + j*4);
            *(float4*)(dst + j*4) = make_float4(v.x*z, v.y*z, v.z*z, v.w*z);
        }
    }
}

// ================== launch ==================
extern "C" void kernel_launch(void* const* d_in, const int* in_sizes, int n_in,
                              void* d_out, int out_size)
{
    const float* q = (const float*)d_in[0];
    const float* k = (const float*)d_in[1];
    const float* v = (const float*)d_in[2];
    const float* p = (const float*)d_in[3];
    float* out = (float*)d_out;

    cudaFuncSetAttribute(k_feat, cudaFuncAttributeMaxDynamicSharedMemorySize, FT_SMEM);
    cudaFuncSetAttribute(k_kv,   cudaFuncAttributeMaxDynamicSharedMemorySize, KV_SMEM);
    cudaFuncSetAttribute(k_out,  cudaFuncAttributeMaxDynamicSharedMemorySize, O_SMEM);

    k_prep<<<8448, 256>>>(q, k, p);
    k_vt<<<dim3(16, HEADS), 256>>>(v);
    k_feat<<<dim3(16, 1, 32), 512, FT_SMEM>>>();
    k_rmax<<<256, 256>>>();
    k_kv<<<dim3(16, HEADS), 256, KV_SMEM>>>();
    k_out<<<dim3(16, HEADS), 256, O_SMEM>>>(out);
}

// round 11
// speedup vs baseline: 1.0157x; 1.0157x over previous
#include <cuda_runtime.h>
#include <cuda_bf16.h>
#include <mma.h>
#include <math_constants.h>
#include <cstdint>

using namespace nvcuda;

#define Nn 2
#define Ll 2048
#define Hh 8
#define Ee 64
#define Mm 2048
#define HEADS 16
#define NLH (HEADS*Ll)

#define NRM   0.3535533905932738f
#define HNRM2 0.0625f
#define RATIO 0.022097086912079608f
#define KEPS  1e-4f
#define EPSZ  1e-6f

// ---------------- scratch ----------------
__device__ float g_Dq[(size_t)HEADS*Ll*Mm];
__device__ float g_Dk[(size_t)HEADS*Ll*Mm];
__device__ float g_diag[2][NLH];
__device__ float g_pmax[(size_t)32*16*Ll];
__device__ float g_SUB[32*Ll];
__device__ __nv_bfloat16 g_Xhi[(size_t)2*HEADS*Ll*Ee];
__device__ __nv_bfloat16 g_Xlo[(size_t)2*HEADS*Ll*Ee];
__device__ __nv_bfloat16 g_Phi[(size_t)Mm*Ee];
__device__ __nv_bfloat16 g_Plo[(size_t)Mm*Ee];
__device__ __nv_bfloat16 g_VThi[(size_t)HEADS*Ee*Ll];
__device__ __nv_bfloat16 g_VTlo[(size_t)HEADS*Ee*Ll];
__device__ __nv_bfloat16 g_Bhi[(size_t)HEADS*80*Mm];   // rows 0-63 kv^T, row 64 ksum
__device__ __nv_bfloat16 g_Blo[(size_t)HEADS*80*Mm];

__device__ __forceinline__ void split1(float v, __nv_bfloat16& hi, __nv_bfloat16& lo) {
    hi = __float2bfloat16_rn(v);
    lo = __float2bfloat16_rn(v - __bfloat162float(hi));
}
__device__ __forceinline__ void split2pack(float a, float b, uint32_t& hi, uint32_t& lo) {
    __nv_bfloat16 ha, la, hb, lb;
    split1(a, ha, la); split1(b, hb, lb);
    __nv_bfloat162 H = __halves2bfloat162(ha, hb), L = __halves2bfloat162(la, lb);
    hi = *(uint32_t*)&H; lo = *(uint32_t*)&L;
}

__device__ __forceinline__ uint32_t smem_u32(const void* p) {
    uint32_t a;
    asm("{ .reg .u64 t; cvta.to.shared.u64 t, %1; cvt.u32.u64 %0, t; }" : "=r"(a) : "l"(p));
    return a;
}
__device__ __forceinline__ void cp16(uint32_t s, const void* g) {
    asm volatile("cp.async.cg.shared.global [%0], [%1], 16;" :: "r"(s), "l"(g));
}
#define CP_COMMIT() asm volatile("cp.async.commit_group;" ::: "memory")
#define CP_WAIT1()  asm volatile("cp.async.wait_group 1;" ::: "memory")
#define CP_WAIT0()  asm volatile("cp.async.wait_group 0;" ::: "memory")
#define BAR_SYNC(id, cnt)   asm volatile("bar.sync %0, %1;"   :: "r"(id), "r"(cnt) : "memory")
#define BAR_ARRIVE(id, cnt) asm volatile("bar.arrive %0, %1;" :: "r"(id), "r"(cnt) : "memory")

typedef wmma::fragment<wmma::matrix_a, 16, 16, 16, __nv_bfloat16, wmma::row_major> FragA;
typedef wmma::fragment<wmma::matrix_a, 16, 16, 16, __nv_bfloat16, wmma::col_major> FragAc;
typedef wmma::fragment<wmma::matrix_b, 16, 16, 16, __nv_bfloat16, wmma::col_major> FragB;
typedef wmma::fragment<wmma::accumulator, 16, 16, 16, float> FragC;

// ================== K0: prep + vT split (merged launch) ==================
// blocks [0, 8448): diag + split X/P.  blocks [8448, 8704): v -> vT split.
__global__ __launch_bounds__(256) void k_prepvt(const float* __restrict__ q,
                                                const float* __restrict__ kk,
                                                const float* __restrict__ P,
                                                const float* __restrict__ V)
{
    __shared__ __nv_bfloat16 sh[2][64][136];
    const int bx = blockIdx.x;
    const int tid = threadIdx.x;

    if (bx < 8448) {
        int g = bx * 256 + tid;
        int w = g >> 5, lane = g & 31;
        if (w < 2*NLH) {
            int which = (w >= NLH) ? 1 : 0;
            int r = which ? (w - NLH) : w;
            int head = r >> 11, l = r & (Ll - 1);
            int n = head >> 3, h = head & 7;
            const float* x = (which ? kk : q) + ((size_t)((n*Ll + l)*Hh + h))*Ee;
            float2 f = *(const float2*)(x + 2*lane);
            float s = f.x*f.x + f.y*f.y;
            #pragma unroll
            for (int o = 16; o; o >>= 1) s += __shfl_xor_sync(0xffffffffu, s, o);
            if (lane == 0) g_diag[which][r] = HNRM2 * s;
            uint32_t hi, lo; split2pack(f.x*NRM, f.y*NRM, hi, lo);
            size_t base = ((size_t)(which*HEADS + head)*Ll + l)*Ee;
            *(uint32_t*)(g_Xhi + base + 2*lane) = hi;
            *(uint32_t*)(g_Xlo + base + 2*lane) = lo;
        } else {
            int m = w - 2*NLH;
            const float* p = P + (size_t)m*Ee;
            float2 f = *(const float2*)(p + 2*lane);
            uint32_t hi, lo; split2pack(f.x, f.y, hi, lo);
            *(uint32_t*)(g_Phi + (size_t)m*Ee + 2*lane) = hi;
            *(uint32_t*)(g_Plo + (size_t)m*Ee + 2*lane) = lo;
        }
    } else {
        const int bvt = bx - 8448;
        const int head = bvt >> 4, n = head >> 3, h = head & 7;
        const int s0 = (bvt & 15) * 128;
        {
            int s = tid >> 1, eh = (tid & 1) * 32;
            const float* vp = V + ((size_t)((n*Ll + s0 + s)*Hh + h))*Ee + eh;
            #pragma unroll
            for (int j = 0; j < 8; j++) {
                float4 f = *(const float4*)(vp + j*4);
                float vv[4] = {f.x, f.y, f.z, f.w};
                #pragma unroll
                for (int i = 0; i < 4; i++) {
                    __nv_bfloat16 hb, lb; split1(vv[i], hb, lb);
                    int e = eh + j*4 + i;
                    sh[0][e][s] = hb;
                    sh[1][e][s] = lb;
                }
            }
        }
        __syncthreads();
        {
            int e = tid >> 2, sc = (tid & 3) * 32;
            #pragma unroll
            for (int p = 0; p < 2; p++) {
                __nv_bfloat16* dst = (p ? g_VTlo : g_VThi) + ((size_t)(head*Ee + e))*Ll + s0 + sc;
                const uint32_t* src = (const uint32_t*)&sh[p][e][sc];
                #pragma unroll
                for (int i = 0; i < 16; i++) ((uint32_t*)dst)[i] = src[i];
            }
        }
    }
}

// ================== K1: featurize — persistent stripe (8 tiles, grid 1024) ==
#define FT_A     36864
#define FT_STG   110592
#define FT_SMEM  178176
__global__ __launch_bounds__(512, 1) void k_feat()
{
    extern __shared__ char smem[];
    const uint32_t sb = smem_u32(smem);
    const int wh = blockIdx.z;
    const int which = wh >> 4, head = wh & 15;
    const int m0 = blockIdx.x * 128;
    const int lbase = blockIdx.y * 1024;
    const int tid = threadIdx.x, wid = tid >> 5;
    float* __restrict__ Dash = which ? g_Dk : g_Dq;

    const __nv_bfloat16* Xhi = g_Xhi + (size_t)wh*Ll*Ee;
    const __nv_bfloat16* Xlo = g_Xlo + (size_t)wh*Ll*Ee;

    #pragma unroll
    for (int j = 0; j < 4; j++) {
        int g = tid + j*512;
        int plane = g >> 10, r = (g >> 3) & 127, c = g & 7;
        const __nv_bfloat16* src = (plane ? g_Plo : g_Phi) + (size_t)(m0 + r)*Ee + c*8;
        cp16(sb + plane*18432 + (r*72 + c*8)*2, src);
    }
    #pragma unroll
    for (int j = 0; j < 4; j++) {
        int g = tid + j*512;
        int plane = g >> 10, r = (g >> 3) & 127, c = g & 7;
        const __nv_bfloat16* src = (plane ? Xlo : Xhi) + (size_t)(lbase + r)*Ee + c*8;
        cp16(sb + FT_A + plane*18432 + (r*72 + c*8)*2, src);
    }
    CP_COMMIT();
    #pragma unroll
    for (int j = 0; j < 4; j++) {
        int g = tid + j*512;
        int plane = g >> 10, r = (g >> 3) & 127, c = g & 7;
        const __nv_bfloat16* src = (plane ? Xlo : Xhi) + (size_t)(lbase + 128 + r)*Ee + c*8;
        cp16(sb + FT_A + 36864 + plane*18432 + (r*72 + c*8)*2, src);
    }
    CP_COMMIT();

    const int warp_l = (wid & 3) * 32, warp_m = (wid >> 2) * 32;
    float* stage = (float*)(smem + FT_STG);
    const __nv_bfloat16* Bhi = (const __nv_bfloat16*)smem;
    const __nv_bfloat16* Blo = Bhi + 9216;

    for (int t = 0; t < 8; t++) {
        if (t < 7) { CP_WAIT1(); } else { CP_WAIT0(); }
        __syncthreads();

        const __nv_bfloat16* Ahi = (const __nv_bfloat16*)(smem + FT_A + (t & 1)*36864);
        const __nv_bfloat16* Alo = Ahi + 9216;

        FragC c[2][2];
        #pragma unroll
        for (int i = 0; i < 2; i++)
            #pragma unroll
            for (int j = 0; j < 2; j++) wmma::fill_fragment(c[i][j], 0.0f);

        #pragma unroll
        for (int k = 0; k < 4; k++) {
            FragA ahi[2], alo[2];
            #pragma unroll
            for (int i = 0; i < 2; i++) {
                wmma::load_matrix_sync(ahi[i], Ahi + (warp_l + i*16)*72 + k*16, 72);
                wmma::load_matrix_sync(alo[i], Alo + (warp_l + i*16)*72 + k*16, 72);
            }
            #pragma unroll
            for (int j = 0; j < 2; j++) {
                FragB bhi, blo;
                wmma::load_matrix_sync(bhi, Bhi + (warp_m + j*16)*72 + k*16, 72);
                wmma::load_matrix_sync(blo, Blo + (warp_m + j*16)*72 + k*16, 72);
                #pragma unroll
                for (int i = 0; i < 2; i++) {
                    wmma::mma_sync(c[i][j], ahi[i], bhi, c[i][j]);
                    wmma::mma_sync(c[i][j], ahi[i], blo, c[i][j]);
                    wmma::mma_sync(c[i][j], alo[i], bhi, c[i][j]);
                }
            }
        }

        #pragma unroll
        for (int i = 0; i < 2; i++)
            #pragma unroll
            for (int j = 0; j < 2; j++)
                wmma::store_matrix_sync(stage + (warp_l + i*16)*132 + warp_m + j*16,
                                        c[i][j], 132, wmma::mem_row_major);
        __syncthreads();

        if (t + 2 < 8) {
            #pragma unroll
            for (int j = 0; j < 4; j++) {
                int g = tid + j*512;
                int plane = g >> 10, r = (g >> 3) & 127, cc = g & 7;
                const __nv_bfloat16* src = (plane ? Xlo : Xhi)
                    + (size_t)(lbase + (t + 2)*128 + r)*Ee + cc*8;
                cp16(sb + FT_A + (t & 1)*36864 + plane*18432 + (r*72 + cc*8)*2, src);
            }
            CP_COMMIT();
        }

        {
            int row = tid >> 2;
            int l = lbase + t*128 + row;
            float rm = -CUDART_INF_F;
            float* dst = Dash + (size_t)(head*Ll + l)*Mm + m0;
            const float* srcr = stage + row*132;
            #pragma unroll
            for (int j = 0; j < 8; j++) {
                int col = (tid & 3)*4 + j*16;
                float4 v = *(const float4*)(srcr + col);
                rm = fmaxf(rm, fmaxf(fmaxf(v.x, v.y), fmaxf(v.z, v.w)));
                *(float4*)(dst + col) = v;
            }
            rm = fmaxf(rm, __shfl_xor_sync(0xffffffffu, rm, 1));
            rm = fmaxf(rm, __shfl_xor_sync(0xffffffffu, rm, 2));
            if ((tid & 3) == 0)
                g_pmax[((size_t)wh*16 + blockIdx.x)*Ll + l] = rm;
        }
    }
}

// ================== K1b: rowmax reduce + diag fold ==================
__global__ __launch_bounds__(256) void k_rmax()
{
    int gw = (blockIdx.x * 256 + threadIdx.x) >> 5;
    int lane = threadIdx.x & 31;
    int wh = gw >> 6;
    int l = (gw & 63) * 32 + lane;
    float m = -CUDART_INF_F;
    #pragma unroll
    for (int mt = 0; mt < 16; mt++)
        m = fmaxf(m, g_pmax[((size_t)wh*16 + mt)*Ll + l]);
    g_SUB[wh*Ll + l] = g_diag[wh >> 4][(wh & 15)*Ll + l] + m;
}

// ================== K2: kv — warp-specialized producer/consumer ==========
#define KV_A    32768
#define KV_B    67584
#define KV_KSS  67584
#define KV_SMEM 98304
__global__ __launch_bounds__(256, 2) void k_kv()
{
    extern __shared__ char smem[];
    const uint32_t sb = smem_u32(smem);

    const int head = blockIdx.y;
    const int m0 = blockIdx.x * 128;
    const int tid = threadIdx.x;

    if (tid >= 128) {
        const int t2 = tid - 128;
        #pragma unroll
        for (int tt = 0; tt < 2; tt++) {
            const float* srcK = g_Dk + (size_t)(head*Ll + tt*32)*Mm + m0;
            uint32_t dK = sb + tt*16384;
            #pragma unroll
            for (int j = 0; j < 8; j++) {
                int g = t2 + j*128, row = g >> 5, col = (g & 31)*4;
                cp16(dK + (row*128 + col)*4, srcK + (size_t)row*Mm + col);
            }
            CP_COMMIT();
        }
    } else {
        #pragma unroll
        for (int tt = 0; tt < 2; tt++) {
            uint32_t dB = sb + KV_B + tt*10240;
            #pragma unroll
            for (int j = 0; j < 4; j++) {
                int g = tid + j*128, plane = g >> 8, rem = g & 255, row = rem >> 2, cc = rem & 3;
                const __nv_bfloat16* src = (plane ? g_VTlo : g_VThi)
                    + (size_t)(head*Ee + row)*Ll + tt*32 + cc*8;
                cp16(dB + plane*5120 + (row*40 + cc*8)*2, src);
            }
            CP_COMMIT();
        }
        BAR_ARRIVE(3, 256);
        BAR_ARRIVE(4, 256);
    }

    float ksp[32];
    FragC c[2][4];

    if (tid >= 128) {
        const int t2 = tid - 128;
        const int s_loc = t2 >> 2, mb = (t2 & 3) * 32;
        const float* SUBp = g_SUB + (16 + head)*Ll + s_loc;
        #pragma unroll
        for (int j = 0; j < 32; j++) ksp[j] = 0.0f;

        for (int t = 0; t < 64; t++) {
            BAR_SYNC(3 + (t & 1), 256);
            if (t < 63) { CP_WAIT1(); } else { CP_WAIT0(); }
            BAR_SYNC(5, 128);

            const float* RK = (const float*)(smem + (t & 1)*16384) + s_loc*128 + mb;
            const float sub = SUBp[t*32];
            char* Abase = smem + KV_A + (t & 1)*17408;
            const uint32_t offb = (uint32_t)(s_loc*136 + mb)*2;
            #pragma unroll
            for (int qq = 0; qq < 4; qq++) {
                float4 f0 = *(const float4*)(RK + qq*8);
                float4 f1 = *(const float4*)(RK + qq*8 + 4);
                float k0 = RATIO * (__expf(f0.x - sub) + KEPS);
                float k1 = RATIO * (__expf(f0.y - sub) + KEPS);
                float k2 = RATIO * (__expf(f0.z - sub) + KEPS);
                float k3 = RATIO * (__expf(f0.w - sub) + KEPS);
                float k4 = RATIO * (__expf(f1.x - sub) + KEPS);
                float k5 = RATIO * (__expf(f1.y - sub) + KEPS);
                float k6 = RATIO * (__expf(f1.z - sub) + KEPS);
                float k7 = RATIO * (__expf(f1.w - sub) + KEPS);
                ksp[qq*8+0] += k0; ksp[qq*8+1] += k1; ksp[qq*8+2] += k2; ksp[qq*8+3] += k3;
                ksp[qq*8+4] += k4; ksp[qq*8+5] += k5; ksp[qq*8+6] += k6; ksp[qq*8+7] += k7;
                uint32_t h0, l0v, h1, l1v, h2, l2v, h3, l3v;
                split2pack(k0, k1, h0, l0v); split2pack(k2, k3, h1, l1v);
                split2pack(k4, k5, h2, l2v); split2pack(k6, k7, h3, l3v);
                *(uint4*)(Abase + offb + qq*16)        = make_uint4(h0, h1, h2, h3);
                *(uint4*)(Abase + 8704 + offb + qq*16) = make_uint4(l0v, l1v, l2v, l3v);
            }
            BAR_SYNC(5, 128);
            if (t + 2 < 64) {
                const float* srcK = g_Dk + (size_t)(head*Ll + (t+2)*32)*Mm + m0;
                uint32_t dK = sb + (t & 1)*16384;
                #pragma unroll
                for (int j = 0; j < 8; j++) {
                    int g = t2 + j*128, row = g >> 5, col = (g & 31)*4;
                    cp16(dK + (row*128 + col)*4, srcK + (size_t)row*Mm + col);
                }
                CP_COMMIT();
            }
            BAR_ARRIVE(1 + (t & 1), 256);
        }
    } else {
        const int wid = tid >> 5;
        const int warp_m = wid * 32;
        #pragma unroll
        for (int i = 0; i < 2; i++)
            #pragma unroll
            for (int j = 0; j < 4; j++) wmma::fill_fragment(c[i][j], 0.0f);

        for (int t = 0; t < 64; t++) {
            if (t < 63) { CP_WAIT1(); } else { CP_WAIT0(); }
            BAR_SYNC(6, 128);
            if (t + 2 < 64) {
                uint32_t dB = sb + KV_B + ((t + 2) % 3)*10240;
                #pragma unroll
                for (int j = 0; j < 4; j++) {
                    int g = tid + j*128, plane = g >> 8, rem = g & 255, row = rem >> 2, cc = rem & 3;
                    const __nv_bfloat16* src = (plane ? g_VTlo : g_VThi)
                        + (size_t)(head*Ee + row)*Ll + (t+2)*32 + cc*8;
                    cp16(dB + plane*5120 + (row*40 + cc*8)*2, src);
                }
                CP_COMMIT();
            }
            BAR_SYNC(1 + (t & 1), 256);

            const __nv_bfloat16* Ahi = (const __nv_bfloat16*)(smem + KV_A + (t & 1)*17408);
            const __nv_bfloat16* Alo = Ahi + 4352;
            const __nv_bfloat16* Bh  = (const __nv_bfloat16*)(smem + KV_B + (t % 3)*10240);
            const __nv_bfloat16* Bl  = Bh + 2560;

            #pragma unroll
            for (int k = 0; k < 2; k++) {
                FragAc ahi[2], alo[2];
                #pragma unroll
                for (int i = 0; i < 2; i++) {
                    wmma::load_matrix_sync(ahi[i], Ahi + (k*16)*136 + warp_m + i*16, 136);
                    wmma::load_matrix_sync(alo[i], Alo + (k*16)*136 + warp_m + i*16, 136);
                }
                #pragma unroll
                for (int j = 0; j < 4; j++) {
                    FragB bhi, blo;
                    wmma::load_matrix_sync(bhi, Bh + (j*16)*40 + k*16, 40);
                    wmma::load_matrix_sync(blo, Bl + (j*16)*40 + k*16, 40);
                    #pragma unroll
                    for (int i = 0; i < 2; i++) {
                        wmma::mma_sync(c[i][j], ahi[i], bhi, c[i][j]);
                        wmma::mma_sync(c[i][j], ahi[i], blo, c[i][j]);
                        wmma::mma_sync(c[i][j], alo[i], bhi, c[i][j]);
                    }
                }
            }
            BAR_ARRIVE(3 + (t & 1), 256);
        }
    }

    __syncthreads();
    float* stage = (float*)smem;
    float* KSS = (float*)(smem + KV_KSS);
    if (tid < 128) {
        const int wid = tid >> 5;
        const int warp_m = wid * 32;
        #pragma unroll
        for (int i = 0; i < 2; i++)
            #pragma unroll
            for (int j = 0; j < 4; j++)
                wmma::store_matrix_sync(stage + (warp_m + i*16) + (j*16)*132,
                                        c[i][j], 132, wmma::mem_col_major);
    } else {
        const int t2 = tid - 128;
        const int s_loc = t2 >> 2, mb = (t2 & 3) * 32;
        #pragma unroll
        for (int j = 0; j < 32; j++) KSS[s_loc*128 + mb + j] = ksp[j];
    }
    __syncthreads();
    {
        int e = tid >> 2, mo = (tid & 3) * 32;
        const float* src = stage + e*132 + mo;
        __nv_bfloat16* dhi = g_Bhi + (size_t)(head*80 + e)*Mm + m0 + mo;
        __nv_bfloat16* dlo = g_Blo + (size_t)(head*80 + e)*Mm + m0 + mo;
        #pragma unroll
        for (int j = 0; j < 32; j += 2) {
            uint32_t hi, lo; split2pack(src[j], src[j+1], hi, lo);
            *(uint32_t*)(dhi + j) = hi;
            *(uint32_t*)(dlo + j) = lo;
        }
    }
    if (tid >= 128) {
        int t2 = tid - 128;
        float s = 0.0f;
        #pragma unroll
        for (int j = 0; j < 32; j++) s += KSS[j*128 + t2];
        __nv_bfloat16 hb, lb; split1(s, hb, lb);
        g_Bhi[(size_t)(head*80 + 64)*Mm + m0 + t2] = hb;
        g_Blo[(size_t)(head*80 + 64)*Mm + m0 + t2] = lb;
    }
}

// ================== K3: out (round-8 structure, N=80 incl. denominator) ====
#define O_AH    36864
#define O_AL    47104
#define O_B     57344
#define O_SUBL  95744
#define O_SMEM  96256
__global__ __launch_bounds__(256, 2) void k_out(float* __restrict__ out)
{
    extern __shared__ char smem[];
    const uint32_t sb = smem_u32(smem);
    __nv_bfloat16* Ah = (__nv_bfloat16*)(smem + O_AH);
    __nv_bfloat16* Al = (__nv_bfloat16*)(smem + O_AL);
    float* SUBL = (float*)(smem + O_SUBL);

    const int head = blockIdx.y, n = head >> 3, h = head & 7;
    const int l0 = blockIdx.x * 128;
    const int tid = threadIdx.x, wid = tid >> 5;

    #pragma unroll
    for (int t = 0; t < 2; t++) {
        const float* srcQ = g_Dq + (size_t)(head*Ll + l0)*Mm + t*32;
        uint32_t dQ = sb + t*18432;
        #pragma unroll
        for (int j = 0; j < 4; j++) {
            int g = tid + j*256, l = g >> 3, col = (g & 7)*4;
            cp16(dQ + (l*36 + col)*4, srcQ + (size_t)l*Mm + col);
        }
        uint32_t dB = sb + O_B + t*12800;
        #pragma unroll
        for (int j = 0; j < 3; j++) {
            int g = tid + j*256;
            if (g < 640) {
                int plane = g / 320, q2 = g % 320, row = q2 >> 2, cc = q2 & 3;
                const __nv_bfloat16* src = (plane ? g_Blo : g_Bhi)
                    + (size_t)(head*80 + row)*Mm + t*32 + cc*8;
                cp16(dB + plane*6400 + (row*40 + cc*8)*2, src);
            }
        }
        CP_COMMIT();
    }

    if (tid < 128)
        SUBL[tid] = g_SUB[head*Ll + l0 + tid];

    const int m2 = (tid & 15) * 2, lg = (tid >> 4) * 8;
    const int warp_l = wid * 16;

    FragC c[5];
    #pragma unroll
    for (int j = 0; j < 5; j++) wmma::fill_fragment(c[j], 0.0f);

    for (int t = 0; t < 64; t++) {
        if (t < 63) { CP_WAIT1(); } else { CP_WAIT0(); }
        __syncthreads();

        const float* RQ = (const float*)(smem + (t & 1)*18432);

        #pragma unroll
        for (int i = 0; i < 8; i++) {
            int l = lg + i;
            float2 f = *(const float2*)(RQ + l*36 + m2);
            float sub = SUBL[l];
            float q0 = RATIO * (__expf(f.x - sub) + KEPS);
            float q1 = RATIO * (__expf(f.y - sub) + KEPS);
            uint32_t hi, lo; split2pack(q0, q1, hi, lo);
            *(uint32_t*)&Ah[l*40 + m2] = hi;
            *(uint32_t*)&Al[l*40 + m2] = lo;
        }
        __syncthreads();

        if (t + 2 < 64) {
            const int m1 = (t + 2) * 32;
            const float* srcQ = g_Dq + (size_t)(head*Ll + l0)*Mm + m1;
            uint32_t dQ = sb + (t & 1)*18432;
            #pragma unroll
            for (int j = 0; j < 4; j++) {
                int g = tid + j*256, l = g >> 3, col = (g & 7)*4;
                cp16(dQ + (l*36 + col)*4, srcQ + (size_t)l*Mm + col);
            }
            uint32_t dB = sb + O_B + ((t + 2) % 3)*12800;
            #pragma unroll
            for (int j = 0; j < 3; j++) {
                int g = tid + j*256;
                if (g < 640) {
                    int plane = g / 320, q2 = g % 320, row = q2 >> 2, cc = q2 & 3;
                    const __nv_bfloat16* src = (plane ? g_Blo : g_Bhi)
                        + (size_t)(head*80 + row)*Mm + m1 + cc*8;
                    cp16(dB + plane*6400 + (row*40 + cc*8)*2, src);
                }
            }
            CP_COMMIT();
        }

        const __nv_bfloat16* Bh = (const __nv_bfloat16*)(smem + O_B + (t % 3)*12800);
        const __nv_bfloat16* Bl = Bh + 3200;

        #pragma unroll
        for (int k = 0; k < 2; k++) {
            FragA ahi, alo;
            wmma::load_matrix_sync(ahi, Ah + warp_l*40 + k*16, 40);
            wmma::load_matrix_sync(alo, Al + warp_l*40 + k*16, 40);
            #pragma unroll
            for (int j = 0; j < 5; j++) {
                FragB bhi, blo;
                wmma::load_matrix_sync(bhi, Bh + (j*16)*40 + k*16, 40);
                wmma::load_matrix_sync(blo, Bl + (j*16)*40 + k*16, 40);
                wmma::mma_sync(c[j], ahi, bhi, c[j]);
                wmma::mma_sync(c[j], ahi, blo, c[j]);
                wmma::mma_sync(c[j], alo, bhi, c[j]);
            }
        }
    }

    __syncthreads();
    float* stage = (float*)smem;  // [l][84]
    #pragma unroll
    for (int j = 0; j < 5; j++)
        wmma::store_matrix_sync(stage + warp_l*84 + j*16, c[j], 84, wmma::mem_row_major);
    __syncthreads();
    {
        int l = tid >> 1, ec = (tid & 1) * 32;
        float z = 1.0f / (stage[l*84 + 64] + EPSZ);
        float* dst = out + ((size_t)((n*Ll + l0 + l)*Hh + h))*Ee + ec;
        const float* src = stage + l*84 + ec;
        #pragma unroll
        for (int j = 0; j < 8; j++) {
            float4 v = *(const float4*)(src + j*4);
            *(float4*)(dst + j*4) = make_float4(v.x*z, v.y*z, v.z*z, v.w*z);
        }
    }
}

// ================== launch ==================
extern "C" void kernel_launch(void* const* d_in, const int* in_sizes, int n_in,
                              void* d_out, int out_size)
{
    const float* q = (const float*)d_in[0];
    const float* k = (const float*)d_in[1];
    const float* v = (const float*)d_in[2];
    const float* p = (const float*)d_in[3];
    float* out = (float*)d_out;

    cudaFuncSetAttribute(k_feat, cudaFuncAttributeMaxDynamicSharedMemorySize, FT_SMEM);
    cudaFuncSetAttribute(k_kv,   cudaFuncAttributeMaxDynamicSharedMemorySize, KV_SMEM);
    cudaFuncSetAttribute(k_out,  cudaFuncAttributeMaxDynamicSharedMemorySize, O_SMEM);

    k_prepvt<<<8704, 256>>>(q, k, p, v);
    k_feat<<<dim3(16, 2, 32), 512, FT_SMEM>>>();
    k_rmax<<<256, 256>>>();
    k_kv<<<dim3(16, HEADS), 256, KV_SMEM>>>();
    k_out<<<dim3(16, HEADS), 256, O_SMEM>>>(out);
}